// round 12
// baseline (speedup 1.0000x reference)
#include <cuda_runtime.h>
#include <cuda_bf16.h>

#define N_EDGES   262144
#define EDGE_DIM  64
#define MAX_PATH  5
#define N_PAIRS   524288
#define OUT_ELEMS 16777216u   // 4096*4096

// Per-(edge, hop) dot table: 262144*5*4 B = 5.24 MB (L2-resident).
__device__ float g_dot[(size_t)N_EDGES * MAX_PATH];

// Kernel A: Ddot[e][l] = dot(edge_attr[e,:], edge_vector[l,:]).
// 4096 blocks x 256 threads: 64 rows/block, 4 lanes per row (16 floats each),
// 2-level shfl reduction within each 4-lane group.
__global__ void __launch_bounds__(256) edge_dot_kernel(
        const float* __restrict__ edge_attr,
        const float* __restrict__ edge_vector) {
    __shared__ float ev[MAX_PATH * EDGE_DIM];
    for (int i = threadIdx.x; i < MAX_PATH * EDGE_DIM; i += 256)
        ev[i] = edge_vector[i];
    __syncthreads();

    const int warp = threadIdx.x >> 5;
    const int lane = threadIdx.x & 31;
    const int j    = lane & 3;
    const int row  = blockIdx.x * 64 + warp * 8 + (lane >> 2);

    const float4* __restrict__ arow =
        reinterpret_cast<const float4*>(edge_attr + (size_t)row * EDGE_DIM + j * 16);

    float s0 = 0.f, s1 = 0.f, s2 = 0.f, s3 = 0.f, s4 = 0.f;
    #pragma unroll
    for (int k = 0; k < 4; k++) {
        const float4 a = arow[k];
        const int co = j * 16 + k * 4;
        #define ACC(L, S) { \
            const float4 e = *reinterpret_cast<const float4*>(ev + (L) * EDGE_DIM + co); \
            S += a.x * e.x + a.y * e.y + a.z * e.z + a.w * e.w; }
        ACC(0, s0) ACC(1, s1) ACC(2, s2) ACC(3, s3) ACC(4, s4)
        #undef ACC
    }

    #pragma unroll
    for (int off = 1; off <= 2; off <<= 1) {
        s0 += __shfl_xor_sync(0xFFFFFFFFu, s0, off);
        s1 += __shfl_xor_sync(0xFFFFFFFFu, s1, off);
        s2 += __shfl_xor_sync(0xFFFFFFFFu, s2, off);
        s3 += __shfl_xor_sync(0xFFFFFFFFu, s3, off);
        s4 += __shfl_xor_sync(0xFFFFFFFFu, s4, off);
    }

    if (j == 0) {
        float* d = g_dot + (size_t)row * MAX_PATH;
        d[0] = s0; d[1] = s1; d[2] = s2; d[3] = s3; d[4] = s4;
    }
}

// Kernel B: 4 pairs per thread. Vectorized int4 index loads (20 ints = 5 int4),
// predicated table gathers (avg 10 in flight per thread), masked mean, scatter.
// Fast path: 4 consecutive & aligned pair_ids -> one float4 store.
__global__ void __launch_bounds__(256) pair_kernel4(
        const int4* __restrict__ path_idx4,   // [N_PAIRS*5/4] int4
        const int4* __restrict__ path_len4,   // [N_PAIRS/4]
        const int4* __restrict__ pair_id4,    // [N_PAIRS/4]
        float* __restrict__ out) {
    const int t = blockIdx.x * blockDim.x + threadIdx.x;   // [0, N_PAIRS/4)

    // 20 path indices for pairs 4t..4t+3
    int idx[20];
    #pragma unroll
    for (int v = 0; v < 5; v++) {
        const int4 q = path_idx4[(size_t)t * 5 + v];
        idx[v * 4 + 0] = q.x & (N_EDGES - 1);
        idx[v * 4 + 1] = q.y & (N_EDGES - 1);
        idx[v * 4 + 2] = q.z & (N_EDGES - 1);
        idx[v * 4 + 3] = q.w & (N_EDGES - 1);
    }
    const int4 len4 = path_len4[t];
    const int4 pid4 = pair_id4[t];
    const int len[4] = {len4.x, len4.y, len4.z, len4.w};

    float val[4];
    #pragma unroll
    for (int i = 0; i < 4; i++) {
        const int* pi = idx + i * 5;
        const int  L  = len[i];
        float s = 0.f;
        if (0 < L) s += __ldg(&g_dot[(size_t)pi[0] * MAX_PATH + 0]);
        if (1 < L) s += __ldg(&g_dot[(size_t)pi[1] * MAX_PATH + 1]);
        if (2 < L) s += __ldg(&g_dot[(size_t)pi[2] * MAX_PATH + 2]);
        if (3 < L) s += __ldg(&g_dot[(size_t)pi[3] * MAX_PATH + 3]);
        if (4 < L) s += __ldg(&g_dot[(size_t)pi[4] * MAX_PATH + 4]);
        val[i] = (L > 0) ? s / (float)L : 0.0f;
    }

    const unsigned o0 = (unsigned)pid4.x & (OUT_ELEMS - 1u);
    if ((pid4.x & 3) == 0 && pid4.y == pid4.x + 1 &&
        pid4.z == pid4.x + 2 && pid4.w == pid4.x + 3) {
        *reinterpret_cast<float4*>(out + o0) =
            make_float4(val[0], val[1], val[2], val[3]);
    } else {
        out[o0] = val[0];
        out[(unsigned)pid4.y & (OUT_ELEMS - 1u)] = val[1];
        out[(unsigned)pid4.z & (OUT_ELEMS - 1u)] = val[2];
        out[(unsigned)pid4.w & (OUT_ELEMS - 1u)] = val[3];
    }
}

extern "C" void kernel_launch(void* const* d_in, const int* in_sizes, int n_in,
                              void* d_out, int out_size) {
    // metadata order: x, edge_attr, edge_vector, path_idx, path_len, pair_id
    const float* edge_attr   = (const float*)d_in[1];
    const float* edge_vector = (const float*)d_in[2];
    const int4*  path_idx4   = (const int4*)d_in[3];
    const int4*  path_len4   = (const int4*)d_in[4];
    const int4*  pair_id4    = (const int4*)d_in[5];
    float* out = (float*)d_out;

    // One-time host-side stream/event creation (host objects, not device memory;
    // happens on the first — uncaptured — correctness call).
    static cudaStream_t s_fork = nullptr;
    static cudaEvent_t  e_root = nullptr, e_join = nullptr;
    if (!s_fork) {
        cudaStreamCreateWithFlags(&s_fork, cudaStreamNonBlocking);
        cudaEventCreateWithFlags(&e_root, cudaEventDisableTiming);
        cudaEventCreateWithFlags(&e_join, cudaEventDisableTiming);
    }

    // Fork: memset (67MB zero of out) runs CONCURRENTLY with kernel A.
    cudaEventRecord(e_root, 0);
    cudaStreamWaitEvent(s_fork, e_root, 0);
    cudaMemsetAsync(out, 0, (size_t)out_size * sizeof(float), s_fork);
    cudaEventRecord(e_join, s_fork);

    // Kernel A on the main (capture) stream, overlapping the memset.
    edge_dot_kernel<<<N_EDGES / 64, 256>>>(edge_attr, edge_vector);

    // Join: B needs both the zeroed output and the dot table.
    cudaStreamWaitEvent(0, e_join, 0);
    pair_kernel4<<<N_PAIRS / 4 / 256, 256>>>(path_idx4, path_len4, pair_id4, out);
}

// round 13
// speedup vs baseline: 1.4478x; 1.4478x over previous
#include <cuda_runtime.h>
#include <cuda_bf16.h>

#define N_EDGES   262144
#define EDGE_DIM  64
#define MAX_PATH  5
#define N_PAIRS   524288
#define OUT_ELEMS 16777216u   // 4096*4096

// Per-(edge, hop) dot table: 262144*5*4 B = 5.24 MB (L2-resident).
__device__ float g_dot[(size_t)N_EDGES * MAX_PATH];

// Fused kernel: (a) zero the 67MB output, (b) Ddot[e][l] = dot(edge_attr[e], ev[l]).
// 4096 blocks x 256 threads. Per warp: 8 rows, 4 lanes per row.
// Lane j of a group reads cols j*4 + k*16 (4 consecutive float4s across lanes
// -> CONFLICT-FREE shared loads of ev, unlike the j*16+k*4 layout which had a
// 2-way bank conflict on every LDS.128).
__global__ void __launch_bounds__(256) edge_dot_zero_kernel(
        const float* __restrict__ edge_attr,
        const float* __restrict__ edge_vector,
        float* __restrict__ out) {
    __shared__ float ev[MAX_PATH * EDGE_DIM];
    for (int i = threadIdx.x; i < MAX_PATH * EDGE_DIM; i += 256)
        ev[i] = edge_vector[i];
    __syncthreads();

    // --- grid-stride zero of the output (exactly 4 float4 per thread) ---
    {
        const size_t tid = (size_t)blockIdx.x * 256 + threadIdx.x;   // [0, 1048576)
        float4* o4 = reinterpret_cast<float4*>(out);
        const float4 z = make_float4(0.f, 0.f, 0.f, 0.f);
        #pragma unroll
        for (int i = 0; i < 4; i++)
            o4[tid + (size_t)i * 1048576] = z;                       // 4*1048576 = OUT/4
    }

    // --- edge-dot tile: 64 rows per block ---
    const int warp = threadIdx.x >> 5;
    const int lane = threadIdx.x & 31;
    const int j    = lane & 3;                        // lane within 4-lane group
    const int row  = blockIdx.x * 64 + warp * 8 + (lane >> 2);

    const float* __restrict__ arow = edge_attr + (size_t)row * EDGE_DIM;

    float s0 = 0.f, s1 = 0.f, s2 = 0.f, s3 = 0.f, s4 = 0.f;
    #pragma unroll
    for (int k = 0; k < 4; k++) {
        const int co = j * 4 + k * 16;                // conflict-free lane layout
        const float4 a = *reinterpret_cast<const float4*>(arow + co);
        #define ACC(L, S) { \
            const float4 e = *reinterpret_cast<const float4*>(ev + (L) * EDGE_DIM + co); \
            S += a.x * e.x + a.y * e.y + a.z * e.z + a.w * e.w; }
        ACC(0, s0) ACC(1, s1) ACC(2, s2) ACC(3, s3) ACC(4, s4)
        #undef ACC
    }

    // reduce within each 4-lane group (xor 1/2 stays inside the group)
    #pragma unroll
    for (int off = 1; off <= 2; off <<= 1) {
        s0 += __shfl_xor_sync(0xFFFFFFFFu, s0, off);
        s1 += __shfl_xor_sync(0xFFFFFFFFu, s1, off);
        s2 += __shfl_xor_sync(0xFFFFFFFFu, s2, off);
        s3 += __shfl_xor_sync(0xFFFFFFFFu, s3, off);
        s4 += __shfl_xor_sync(0xFFFFFFFFu, s4, off);
    }

    if (j == 0) {
        float* d = g_dot + (size_t)row * MAX_PATH;
        d[0] = s0; d[1] = s1; d[2] = s2; d[3] = s3; d[4] = s4;
    }
}

// Kernel B: 2 pairs per thread (262144 threads -> ~84% occupancy vs 42% at
// 4/thread), int2 index loads, predicated gathers (~5 avg in flight/thread),
// masked mean, scatter. Fast path: consecutive even-aligned pair_ids -> float2.
__global__ void __launch_bounds__(256) pair_kernel2(
        const int2* __restrict__ path_idx2,   // 5 int2 per thread
        const int2* __restrict__ path_len2,
        const int2* __restrict__ pair_id2,
        float* __restrict__ out) {
    const int t = blockIdx.x * blockDim.x + threadIdx.x;   // [0, N_PAIRS/2)

    // 10 path indices for pairs 2t, 2t+1 (5 aligned int2 loads)
    int idx[10];
    #pragma unroll
    for (int v = 0; v < 5; v++) {
        const int2 q = path_idx2[(size_t)t * 5 + v];
        idx[v * 2 + 0] = q.x & (N_EDGES - 1);
        idx[v * 2 + 1] = q.y & (N_EDGES - 1);
    }
    const int2 len2 = path_len2[t];
    const int2 pid2 = pair_id2[t];
    const int len[2] = {len2.x, len2.y};

    float val[2];
    #pragma unroll
    for (int i = 0; i < 2; i++) {
        const int* pi = idx + i * 5;
        const int  L  = len[i];
        float s = 0.f;
        if (0 < L) s += __ldg(&g_dot[(size_t)pi[0] * MAX_PATH + 0]);
        if (1 < L) s += __ldg(&g_dot[(size_t)pi[1] * MAX_PATH + 1]);
        if (2 < L) s += __ldg(&g_dot[(size_t)pi[2] * MAX_PATH + 2]);
        if (3 < L) s += __ldg(&g_dot[(size_t)pi[3] * MAX_PATH + 3]);
        if (4 < L) s += __ldg(&g_dot[(size_t)pi[4] * MAX_PATH + 4]);
        val[i] = (L > 0) ? s / (float)L : 0.0f;
    }

    const unsigned o0 = (unsigned)pid2.x & (OUT_ELEMS - 1u);
    if ((pid2.x & 1) == 0 && pid2.y == pid2.x + 1) {
        *reinterpret_cast<float2*>(out + o0) = make_float2(val[0], val[1]);
    } else {
        out[o0] = val[0];
        out[(unsigned)pid2.y & (OUT_ELEMS - 1u)] = val[1];
    }
}

extern "C" void kernel_launch(void* const* d_in, const int* in_sizes, int n_in,
                              void* d_out, int out_size) {
    // metadata order: x, edge_attr, edge_vector, path_idx, path_len, pair_id
    const float* edge_attr   = (const float*)d_in[1];
    const float* edge_vector = (const float*)d_in[2];
    const int2*  path_idx2   = (const int2*)d_in[3];
    const int2*  path_len2   = (const int2*)d_in[4];
    const int2*  pair_id2    = (const int2*)d_in[5];
    float* out = (float*)d_out;

    // Fused: output zeroing + edge-hop dot table (best measured structure).
    edge_dot_zero_kernel<<<4096, 256>>>(edge_attr, edge_vector, out);

    // Per-pair gather/scatter: 2 pairs/thread, 1024 blocks.
    pair_kernel2<<<N_PAIRS / 2 / 256, 256>>>(path_idx2, path_len2, pair_id2, out);
}

// round 14
// speedup vs baseline: 1.4863x; 1.0266x over previous
#include <cuda_runtime.h>
#include <cuda_bf16.h>

#define N_EDGES   262144
#define EDGE_DIM  64
#define MAX_PATH  5
#define N_PAIRS   524288
#define OUT_ELEMS 16777216u   // 4096*4096

// Per-(edge, hop) dot table: 262144*5*4 B = 5.24 MB (L2-resident).
__device__ float g_dot[(size_t)N_EDGES * MAX_PATH];

// Fused kernel: (a) zero the 67MB output, (b) Ddot[e][l] = dot(edge_attr[e], ev[l]).
// 4096 blocks x 256 threads. Per warp: 8 rows, 4 lanes per row.
// Lane j of a group reads cols j*4 + k*16 (4 consecutive float4s across lanes
// -> CONFLICT-FREE shared loads of ev, unlike the j*16+k*4 layout which had a
// 2-way bank conflict on every LDS.128).
__global__ void __launch_bounds__(256) edge_dot_zero_kernel(
        const float* __restrict__ edge_attr,
        const float* __restrict__ edge_vector,
        float* __restrict__ out) {
    __shared__ float ev[MAX_PATH * EDGE_DIM];
    for (int i = threadIdx.x; i < MAX_PATH * EDGE_DIM; i += 256)
        ev[i] = edge_vector[i];
    __syncthreads();

    // --- grid-stride zero of the output (exactly 4 float4 per thread) ---
    {
        const size_t tid = (size_t)blockIdx.x * 256 + threadIdx.x;   // [0, 1048576)
        float4* o4 = reinterpret_cast<float4*>(out);
        const float4 z = make_float4(0.f, 0.f, 0.f, 0.f);
        #pragma unroll
        for (int i = 0; i < 4; i++)
            o4[tid + (size_t)i * 1048576] = z;                       // 4*1048576 = OUT/4
    }

    // --- edge-dot tile: 64 rows per block ---
    const int warp = threadIdx.x >> 5;
    const int lane = threadIdx.x & 31;
    const int j    = lane & 3;                        // lane within 4-lane group
    const int row  = blockIdx.x * 64 + warp * 8 + (lane >> 2);

    const float* __restrict__ arow = edge_attr + (size_t)row * EDGE_DIM;

    float s0 = 0.f, s1 = 0.f, s2 = 0.f, s3 = 0.f, s4 = 0.f;
    #pragma unroll
    for (int k = 0; k < 4; k++) {
        const int co = j * 4 + k * 16;                // conflict-free lane layout
        const float4 a = *reinterpret_cast<const float4*>(arow + co);
        #define ACC(L, S) { \
            const float4 e = *reinterpret_cast<const float4*>(ev + (L) * EDGE_DIM + co); \
            S += a.x * e.x + a.y * e.y + a.z * e.z + a.w * e.w; }
        ACC(0, s0) ACC(1, s1) ACC(2, s2) ACC(3, s3) ACC(4, s4)
        #undef ACC
    }

    // reduce within each 4-lane group (xor 1/2 stays inside the group)
    #pragma unroll
    for (int off = 1; off <= 2; off <<= 1) {
        s0 += __shfl_xor_sync(0xFFFFFFFFu, s0, off);
        s1 += __shfl_xor_sync(0xFFFFFFFFu, s1, off);
        s2 += __shfl_xor_sync(0xFFFFFFFFu, s2, off);
        s3 += __shfl_xor_sync(0xFFFFFFFFu, s3, off);
        s4 += __shfl_xor_sync(0xFFFFFFFFu, s4, off);
    }

    if (j == 0) {
        float* d = g_dot + (size_t)row * MAX_PATH;
        d[0] = s0; d[1] = s1; d[2] = s2; d[3] = s3; d[4] = s4;
    }
}

// Kernel B: 2 pairs per thread (262144 threads -> ~84% occupancy vs 42% at
// 4/thread), int2 index loads, predicated gathers (~5 avg in flight/thread),
// masked mean, scatter. Fast path: consecutive even-aligned pair_ids -> float2.
__global__ void __launch_bounds__(256) pair_kernel2(
        const int2* __restrict__ path_idx2,   // 5 int2 per thread
        const int2* __restrict__ path_len2,
        const int2* __restrict__ pair_id2,
        float* __restrict__ out) {
    const int t = blockIdx.x * blockDim.x + threadIdx.x;   // [0, N_PAIRS/2)

    // 10 path indices for pairs 2t, 2t+1 (5 aligned int2 loads)
    int idx[10];
    #pragma unroll
    for (int v = 0; v < 5; v++) {
        const int2 q = path_idx2[(size_t)t * 5 + v];
        idx[v * 2 + 0] = q.x & (N_EDGES - 1);
        idx[v * 2 + 1] = q.y & (N_EDGES - 1);
    }
    const int2 len2 = path_len2[t];
    const int2 pid2 = pair_id2[t];
    const int len[2] = {len2.x, len2.y};

    float val[2];
    #pragma unroll
    for (int i = 0; i < 2; i++) {
        const int* pi = idx + i * 5;
        const int  L  = len[i];
        float s = 0.f;
        if (0 < L) s += __ldg(&g_dot[(size_t)pi[0] * MAX_PATH + 0]);
        if (1 < L) s += __ldg(&g_dot[(size_t)pi[1] * MAX_PATH + 1]);
        if (2 < L) s += __ldg(&g_dot[(size_t)pi[2] * MAX_PATH + 2]);
        if (3 < L) s += __ldg(&g_dot[(size_t)pi[3] * MAX_PATH + 3]);
        if (4 < L) s += __ldg(&g_dot[(size_t)pi[4] * MAX_PATH + 4]);
        val[i] = (L > 0) ? s / (float)L : 0.0f;
    }

    const unsigned o0 = (unsigned)pid2.x & (OUT_ELEMS - 1u);
    if ((pid2.x & 1) == 0 && pid2.y == pid2.x + 1) {
        *reinterpret_cast<float2*>(out + o0) = make_float2(val[0], val[1]);
    } else {
        out[o0] = val[0];
        out[(unsigned)pid2.y & (OUT_ELEMS - 1u)] = val[1];
    }
}

extern "C" void kernel_launch(void* const* d_in, const int* in_sizes, int n_in,
                              void* d_out, int out_size) {
    // metadata order: x, edge_attr, edge_vector, path_idx, path_len, pair_id
    const float* edge_attr   = (const float*)d_in[1];
    const float* edge_vector = (const float*)d_in[2];
    const int2*  path_idx2   = (const int2*)d_in[3];
    const int2*  path_len2   = (const int2*)d_in[4];
    const int2*  pair_id2    = (const int2*)d_in[5];
    float* out = (float*)d_out;

    // Fused: output zeroing + edge-hop dot table (best measured structure).
    edge_dot_zero_kernel<<<4096, 256>>>(edge_attr, edge_vector, out);

    // Per-pair gather/scatter: 2 pairs/thread, 1024 blocks.
    pair_kernel2<<<N_PAIRS / 2 / 256, 256>>>(path_idx2, path_len2, pair_id2, out);
}